// round 13
// baseline (speedup 1.0000x reference)
#include <cuda_runtime.h>
#include <cuda_bf16.h>
#include <cstdint>

#define N_NODES 2048
#define NQ (N_NODES / 4)          // 512 float4 per row
#define EPS 0.01f
#define THREADS 512               // one thread per float4 column
#define CTAS_PER_SM 2
#define CHUNKS 37                 // per batch -> 8*37 = 296 CTAs = 148 SMs * 2

__device__ unsigned long long g_combined = 0ULL;  // [arrivals:32 | count:32]

__device__ __forceinline__ int pair4(const float4 w, const float pi, const float4 pj)
{
    int c = 0;
    c += (w.x == 1.0f) & (fabsf(pi - pj.x) < EPS);
    c += (w.y == 1.0f) & (fabsf(pi - pj.y) < EPS);
    c += (w.z == 1.0f) & (fabsf(pi - pj.z) < EPS);
    c += (w.w == 1.0f) & (fabsf(pi - pj.w) < EPS);
    return c;
}

__global__ void __launch_bounds__(THREADS, CTAS_PER_SM) count_kernel(
    const float* __restrict__ W, const float* __restrict__ pred,
    float* __restrict__ out, int nblocks)
{
    const int bid = blockIdx.x;
    const int b   = bid / CHUNKS;
    const int c   = bid % CHUNKS;
    const int start = (c * N_NODES) / CHUNKS;
    const int end   = ((c + 1) * N_NODES) / CHUNKS;   // 55 or 56 rows, same batch
    const int tid = threadIdx.x;

    const float* predb = pred + ((size_t)b << 11);
    const float4* Wt = (const float4*)(W + (size_t)(2 * b + 1) * (size_t)N_NODES * N_NODES)
                       + (size_t)start * NQ + tid;

    // --- prologue: start the W stream FIRST (DRAM busy from cycle ~0) ---
    float4 w0[2];
    float  pi[2];
    w0[0] = __ldcs(Wt);

    // this thread's fixed column group (L2-hot after first CTA of each batch)
    const float4 pj0 = __ldg((const float4*)predb + tid);
    pi[0] = __ldg(predb + start);

    int cnt = 0;
    int p = 0;
    #pragma unroll 2
    for (int r = start; r < end; ++r) {
        const int nxt = p ^ 1;
        if (r + 1 < end) {
            w0[nxt] = __ldcs(Wt + (size_t)(r + 1 - start) * NQ);
            pi[nxt] = __ldg(predb + r + 1);
        }
        cnt += pair4(w0[p], pi[p], pj0);
        p = nxt;
    }

    // block reduce
    #pragma unroll
    for (int o = 16; o > 0; o >>= 1)
        cnt += __shfl_xor_sync(0xffffffffu, cnt, o);

    __shared__ int warpsum[THREADS / 32];
    if ((tid & 31) == 0)
        warpsum[tid >> 5] = cnt;
    __syncthreads();

    if (tid == 0) {
        int v = 0;
        #pragma unroll
        for (int i = 0; i < THREADS / 32; ++i)
            v += warpsum[i];
        // one packed RMW: arrivals in high 32, count in low 32. RMW total order
        // guarantees the last arriver's return value holds the full sum.
        unsigned long long old =
            atomicAdd(&g_combined, (1ULL << 32) | (unsigned long long)(unsigned)v);
        if ((unsigned)(old >> 32) == (unsigned)(nblocks - 1)) {
            const unsigned total = (unsigned)old + (unsigned)v;
            out[0] = (float)total;
            g_combined = 0ULL;   // reset for next graph replay (deterministic)
        }
    }
}

extern "C" void kernel_launch(void* const* d_in, const int* in_sizes, int n_in,
                              void* d_out, int out_size)
{
    const float* W    = (const float*)d_in[0];
    const float* pred = (const float*)d_in[1];
    float* out = (float*)d_out;

    const int B = in_sizes[1] / N_NODES;
    const int nblocks = B * CHUNKS;     // 296
    count_kernel<<<nblocks, THREADS>>>(W, pred, out, nblocks);
}

// round 14
// speedup vs baseline: 1.0965x; 1.0965x over previous
#include <cuda_runtime.h>
#include <cuda_bf16.h>
#include <cstdint>

#define N_NODES 2048
#define NQ (N_NODES / 4)          // 512 float4 per row
#define EPS 0.01f
#define THREADS 256
#define CHUNKS 74                 // per batch -> 8*74 = 592 CTAs = 148 SMs * 4

__device__ unsigned long long g_combined = 0ULL;  // [arrivals:32 | count:32]

struct f8 { float4 a, b; };

// Blackwell 256-bit streaming load (sm_100+): one LDG.256 per row per thread.
__device__ __forceinline__ f8 ldg256_cs(const float* p)
{
    f8 r;
    asm volatile(
        "ld.global.cs.v8.f32 {%0,%1,%2,%3,%4,%5,%6,%7}, [%8];"
        : "=f"(r.a.x), "=f"(r.a.y), "=f"(r.a.z), "=f"(r.a.w),
          "=f"(r.b.x), "=f"(r.b.y), "=f"(r.b.z), "=f"(r.b.w)
        : "l"(p));
    return r;
}

__device__ __forceinline__ int pair4(const float4 w, const float pi, const float4 pj)
{
    int c = 0;
    c += (w.x == 1.0f) & (fabsf(pi - pj.x) < EPS);
    c += (w.y == 1.0f) & (fabsf(pi - pj.y) < EPS);
    c += (w.z == 1.0f) & (fabsf(pi - pj.z) < EPS);
    c += (w.w == 1.0f) & (fabsf(pi - pj.w) < EPS);
    return c;
}

__global__ void __launch_bounds__(THREADS, 4) count_kernel(
    const float* __restrict__ W, const float* __restrict__ pred,
    float* __restrict__ out, int nblocks)
{
    const int bid = blockIdx.x;
    const int b   = bid / CHUNKS;
    const int c   = bid % CHUNKS;
    const int start = (c * N_NODES) / CHUNKS;
    const int end   = ((c + 1) * N_NODES) / CHUNKS;   // 27 or 28 rows, same batch
    const int tid = threadIdx.x;

    const float* predb = pred + ((size_t)b << 11);
    // this thread owns 8 contiguous floats per row, at element offset tid*8
    const float* Wt = W + (size_t)(2 * b + 1) * (size_t)N_NODES * N_NODES
                      + (size_t)start * N_NODES + (size_t)tid * 8;

    // --- prologue: start the W stream FIRST (DRAM busy from cycle ~0) ---
    f8    w[2];
    float pi[2];
    w[0] = ldg256_cs(Wt);

    // per-thread fixed column groups: 8 contiguous pred values (registers)
    const float4 pj0 = __ldg((const float4*)predb + 2 * tid);
    const float4 pj1 = __ldg((const float4*)predb + 2 * tid + 1);
    pi[0] = __ldg(predb + start);

    int cnt = 0;
    int p = 0;
    #pragma unroll 2
    for (int r = start; r < end; ++r) {
        const int nxt = p ^ 1;
        if (r + 1 < end) {
            w[nxt]  = ldg256_cs(Wt + (size_t)(r + 1 - start) * N_NODES);
            pi[nxt] = __ldg(predb + r + 1);
        }
        cnt += pair4(w[p].a, pi[p], pj0);
        cnt += pair4(w[p].b, pi[p], pj1);
        p = nxt;
    }

    // block reduce
    #pragma unroll
    for (int o = 16; o > 0; o >>= 1)
        cnt += __shfl_xor_sync(0xffffffffu, cnt, o);

    __shared__ int warpsum[THREADS / 32];
    if ((tid & 31) == 0)
        warpsum[tid >> 5] = cnt;
    __syncthreads();

    if (tid == 0) {
        int v = 0;
        #pragma unroll
        for (int i = 0; i < THREADS / 32; ++i)
            v += warpsum[i];
        // one packed RMW: arrivals in high 32, count in low 32. RMW total order
        // guarantees the last arriver's return value holds the full sum.
        unsigned long long old =
            atomicAdd(&g_combined, (1ULL << 32) | (unsigned long long)(unsigned)v);
        if ((unsigned)(old >> 32) == (unsigned)(nblocks - 1)) {
            const unsigned total = (unsigned)old + (unsigned)v;
            out[0] = (float)total;
            g_combined = 0ULL;   // reset for next graph replay (deterministic)
        }
    }
}

extern "C" void kernel_launch(void* const* d_in, const int* in_sizes, int n_in,
                              void* d_out, int out_size)
{
    const float* W    = (const float*)d_in[0];
    const float* pred = (const float*)d_in[1];
    float* out = (float*)d_out;

    const int B = in_sizes[1] / N_NODES;
    const int nblocks = B * CHUNKS;     // 592
    count_kernel<<<nblocks, THREADS>>>(W, pred, out, nblocks);
}